// round 5
// baseline (speedup 1.0000x reference)
#include <cuda_runtime.h>
#include <stdint.h>

#define NB 256
#define LL 1024
#define TT 128
#define THREADS 128
#define FULL 0xffffffffu

// dynamic smem layout (bytes)
#define OFF_TRANS 0                         // 128*128*4 = 65536 (row-major, as in gmem)
#define OFF_BP    65536                     // 1024*128 int8 = 131072
#define OFF_TAGS  (65536 + 131072)          // 1024*4 = 4096
#define OFF_RED   (OFF_TAGS + 4096)         // 1024 bytes staging
#define SMEM_BYTES (OFF_RED + 1024)         // 201728

// order-preserving float <-> uint map (for __reduce_{max,min}_sync)
__device__ __forceinline__ unsigned fmap(float f) {
    unsigned u = __float_as_uint(f);
    return (u & 0x80000000u) ? ~u : (u | 0x80000000u);
}
__device__ __forceinline__ float funmap(unsigned u) {
    return __uint_as_float((u & 0x80000000u) ? (u ^ 0x80000000u) : ~u);
}

__device__ __forceinline__ void upd(float &bv, int &bi, float sc, int i) {
    // first-argmax semantics: strictly better, or equal with smaller index
    bool better = (sc > bv) || ((sc == bv) && (i < bi));
    bv = better ? sc : bv;
    bi = better ? i : bi;
}

__global__ __launch_bounds__(THREADS, 1)
void crf_decode_kernel(const float* __restrict__ x,
                       const int* __restrict__ lengths,
                       const float* __restrict__ trans,
                       float* __restrict__ out)          // float32 output (validated)
{
    extern __shared__ char smem[];
    float*   s_trans = (float*)(smem + OFF_TRANS);
    uint8_t* s_bp    = (uint8_t*)(smem + OFF_BP);
    int*     s_tags  = (int*)(smem + OFF_TAGS);
    float*   s_red   = (float*)(smem + OFF_RED);        // [0..127] mx, [128..255] mn

    const int tid = threadIdx.x;
    const int b   = blockIdx.x;

    int len = lengths[b];
    if (len > LL) len = LL;
    if (len < 1)  len = 1;

    // ---- cooperative load of trans into smem + per-thread min/max fold ----
    {
        float mx = -3.4e38f, mn = 3.4e38f;
        const float4* t4  = (const float4*)trans;
        float4*       st4 = (float4*)s_trans;
        #pragma unroll 8
        for (int k = tid; k < (TT * TT / 4); k += THREADS) {
            float4 v = t4[k];
            st4[k] = v;
            mx = fmaxf(mx, fmaxf(fmaxf(v.x, v.y), fmaxf(v.z, v.w)));
            mn = fminf(mn, fminf(fminf(v.x, v.y), fminf(v.z, v.w)));
        }
        s_red[tid]       = mx;
        s_red[128 + tid] = mn;
    }
    __syncthreads();

    // ================= forward recurrence: warp 0 only, no block barriers =================
    if (tid < 32) {
        const int lane = tid;

        // combine min/max from staging: each lane folds 4 entries, then warp redux
        float mx = -3.4e38f, mn = 3.4e38f;
        #pragma unroll
        for (int c = 0; c < 4; ++c) {
            mx = fmaxf(mx, s_red[lane * 4 + c]);
            mn = fminf(mn, s_red[128 + lane * 4 + c]);
        }
        mx = funmap(__reduce_max_sync(FULL, fmap(mx)));
        mn = -funmap(__reduce_max_sync(FULL, fmap(-mn)));
        float D = (mx - mn) * 1.001f + 0.01f;           // exact-pruning width + fp margin
        if (!(D >= 0.01f && D <= 1000.0f)) D = 3.0e38f; // dense fallback if anomalous

        const float* xrow = x + (size_t)b * (LL * TT);

        // state i = 4*lane + c, held in s0..s3
        float4 xc = ((const float4*)xrow)[lane];
        float s0 = xc.x, s1 = xc.y, s2 = xc.z, s3 = xc.w;

        // depth-3 prefetch of x rows (all consumed loads are range-guarded)
        float4 xp0 = make_float4(0,0,0,0), xp1 = xp0, xp2 = xp0;
        if (len > 1) xp0 = ((const float4*)(xrow + (size_t)1 * TT))[lane];
        if (len > 2) xp1 = ((const float4*)(xrow + (size_t)2 * TT))[lane];
        if (len > 3) xp2 = ((const float4*)(xrow + (size_t)3 * TT))[lane];

        const float* tbase = s_trans + (lane << 2);     // this lane's 4 target columns

        for (int t = 1; t < len; ++t) {
            float4 xt = xp0;
            xp0 = xp1; xp1 = xp2;
            if (t + 3 < len) xp2 = ((const float4*)(xrow + (size_t)(t + 3) * TT))[lane];

            // warp max of 128 states: local max-of-4 + one redux
            float lm = fmaxf(fmaxf(s0, s1), fmaxf(s2, s3));
            lm = funmap(__reduce_max_sync(FULL, fmap(lm)));
            float thr = lm - D;

            unsigned m0 = __ballot_sync(FULL, s0 >= thr);
            unsigned m1 = __ballot_sync(FULL, s1 >= thr);
            unsigned m2 = __ballot_sync(FULL, s2 >= thr);
            unsigned m3 = __ballot_sync(FULL, s3 >= thr);
            if ((m0 | m1 | m2 | m3) == 0u)              // unreachable with sane D
                m0 = m1 = m2 = m3 = 0xffffffffu;

            float bv0 = -3.4e38f, bv1 = -3.4e38f, bv2 = -3.4e38f, bv3 = -3.4e38f;
            int   bi0 = 0x7fffffff, bi1 = 0x7fffffff, bi2 = 0x7fffffff, bi3 = 0x7fffffff;

            // score survivors only; masks are warp-uniform -> fully converged loops.
            // tie order irrelevant: upd() compares indices on exact ties.
            #define PROC(MASK, SREG, C)                                        \
            { unsigned mm = (MASK);                                            \
              while (mm) {                                                     \
                  int l2 = __ffs(mm) - 1; mm &= mm - 1;                        \
                  int i  = (l2 << 2) + (C);                                    \
                  float v = __shfl_sync(FULL, SREG, l2);                       \
                  float4 tr = *(const float4*)(tbase + (i << 7));              \
                  upd(bv0, bi0, v + tr.x, i);                                  \
                  upd(bv1, bi1, v + tr.y, i);                                  \
                  upd(bv2, bi2, v + tr.z, i);                                  \
                  upd(bv3, bi3, v + tr.w, i);                                  \
              } }
            PROC(m0, s0, 0)
            PROC(m1, s1, 1)
            PROC(m2, s2, 2)
            PROC(m3, s3, 3)
            #undef PROC

            s0 = bv0 + xt.x;
            s1 = bv1 + xt.y;
            s2 = bv2 + xt.z;
            s3 = bv3 + xt.w;

            // pack 4 backpointers -> byte j of row t (j = 4*lane + c)
            unsigned bpw = (unsigned)bi0 | ((unsigned)bi1 << 8) |
                           ((unsigned)bi2 << 16) | ((unsigned)bi3 << 24);
            ((unsigned*)s_bp)[(t << 5) + lane] = bpw;
        }

        // final argmax over state, first-max index
        float fm = fmaxf(fmaxf(s0, s1), fmaxf(s2, s3));
        fm = funmap(__reduce_max_sync(FULL, fmap(fm)));
        int cand = 0x7fffffff;
        if (s3 == fm) cand = (lane << 2) + 3;
        if (s2 == fm) cand = (lane << 2) + 2;
        if (s1 == fm) cand = (lane << 2) + 1;
        if (s0 == fm) cand = (lane << 2) + 0;
        cand = (int)__reduce_min_sync(FULL, (unsigned)cand);
        if (cand > TT - 1) cand = 0;                    // safety, unreachable

        // backward walk: smem pointer chase, lane 0
        if (lane == 0) {
            int carry = cand;
            for (int t = len - 1; t >= 1; --t) {
                s_tags[t] = carry;
                carry = (int)s_bp[(t << 7) + carry];
            }
            s_tags[0] = carry;
        }
    }
    __syncthreads();

    // ---- output: float32 tags for t < len, zeros beyond ----
    float* orow = out + b * LL;
    #pragma unroll 2
    for (int k = tid; k < LL / 4; k += THREADS) {
        int base = k << 2;
        float4 v;
        v.x = (base + 0 < len) ? (float)s_tags[base + 0] : 0.0f;
        v.y = (base + 1 < len) ? (float)s_tags[base + 1] : 0.0f;
        v.z = (base + 2 < len) ? (float)s_tags[base + 2] : 0.0f;
        v.w = (base + 3 < len) ? (float)s_tags[base + 3] : 0.0f;
        ((float4*)orow)[k] = v;
    }
}

extern "C" void kernel_launch(void* const* d_in, const int* in_sizes, int n_in,
                              void* d_out, int out_size)
{
    // Size-based identification (element counts or byte counts); positional fallback.
    const float* x       = nullptr;
    const int*   lengths = nullptr;
    const float* trans   = nullptr;
    for (int i = 0; i < n_in; ++i) {
        long s = in_sizes[i];
        if      (s == 33554432L || s == 134217728L) x       = (const float*)d_in[i];
        else if (s == 256L      || s == 1024L)      lengths = (const int*)d_in[i];
        else if (s == 16384L    || s == 65536L)     trans   = (const float*)d_in[i];
        // 262144 / 1048576 = tags (unused)
    }
    if (!x       && n_in > 0) x       = (const float*)d_in[0];
    if (!lengths && n_in > 1) lengths = (const int*)d_in[1];
    if (!trans   && n_in > 3) trans   = (const float*)d_in[3];

    cudaFuncSetAttribute(crf_decode_kernel,
                         cudaFuncAttributeMaxDynamicSharedMemorySize, SMEM_BYTES);
    crf_decode_kernel<<<NB, THREADS, SMEM_BYTES>>>(x, lengths, trans, (float*)d_out);
}

// round 7
// speedup vs baseline: 1.9883x; 1.9883x over previous
#include <cuda_runtime.h>
#include <stdint.h>

#define NB 256
#define LL 1024
#define TT 128
#define THREADS 128
#define TSTRIDE 129
#define FULL 0xffffffffu

// smem layout (bytes) -- every section 16B-aligned (LDS.128 safety)
#define OFF_TRANST 0                               // 128*129*4 = 66048 (16B-aligned size)
#define OFF_BP     66048                           // 1024*128 = 131072
#define OFF_TAGS   (66048 + 131072)                // 197120, size 4096
#define OFF_WMAX   (OFF_TAGS + 4096)               // 201216, size 16
#define OFF_CNT    (OFF_WMAX + 16)                 // 201232, size 16 (2 ints + pad)
#define OFF_SURV   (OFF_CNT + 16)                  // 201248 (mult of 16), size 2*128*8 = 2048
#define OFF_RED    (OFF_SURV + 2048)               // 203296 (mult of 16), size 1024
#define SMEM_BYTES (OFF_RED + 1024)                // 204320

__device__ int d_sched[NB];

// order-preserving float <-> uint map
__device__ __forceinline__ unsigned fmap(float f) {
    unsigned u = __float_as_uint(f);
    return (u & 0x80000000u) ? ~u : (u | 0x80000000u);
}
__device__ __forceinline__ float funmap(unsigned u) {
    return __uint_as_float((u & 0x80000000u) ? (u ^ 0x80000000u) : ~u);
}

__device__ __forceinline__ void upd(float &bv, int &bi, float sc, int i) {
    // first-argmax: strictly better, or equal with smaller index (order-independent)
    bool better = (sc > bv) || ((sc == bv) && (i < bi));
    bv = better ? sc : bv;
    bi = better ? i : bi;
}

// ---- pre-kernel: LPT schedule (bitonic sort of 256 keys, descending by length) ----
__global__ void sched_kernel(const int* __restrict__ lengths)
{
    __shared__ unsigned key[NB];
    int i = threadIdx.x;
    unsigned l = (unsigned)max(0, min(LL, lengths[i]));
    key[i] = (l << 8) | (255u - (unsigned)i);      // desc len, asc idx on ties
    __syncthreads();
    for (int k = 2; k <= NB; k <<= 1) {
        for (int j = k >> 1; j > 0; j >>= 1) {
            int ixj = i ^ j;
            if (ixj > i) {
                unsigned a = key[i], b2 = key[ixj];
                bool up = ((i & k) == 0);
                bool sw = up ? (a < b2) : (a > b2); // descending overall
                if (sw) { key[i] = b2; key[ixj] = a; }
            }
            __syncthreads();
        }
    }
    d_sched[i] = 255 - (int)(key[i] & 0xFFu);
}

__global__ __launch_bounds__(THREADS, 1)
void crf_decode_kernel(const float* __restrict__ x,
                       const int* __restrict__ lengths,
                       const float* __restrict__ trans,
                       float* __restrict__ out)
{
    extern __shared__ char smem[];
    float*    s_transT = (float*)(smem + OFF_TRANST);   // [j][i] stride 129 (conflict-free)
    uint8_t*  s_bp     = (uint8_t*)(smem + OFF_BP);
    int*      s_tags   = (int*)(smem + OFF_TAGS);
    unsigned* s_wmax   = (unsigned*)(smem + OFF_WMAX);  // 4 warp maxima
    int*      s_cnt    = (int*)(smem + OFF_CNT);        // double-buffered counters
    int2*     s_surv   = (int2*)(smem + OFF_SURV);      // [2][128] (valbits, idx)
    float*    s_red    = (float*)(smem + OFF_RED);      // mx[128], mn[128] / final state

    const int tid  = threadIdx.x;
    const int lane = tid & 31;
    const int w    = tid >> 5;
    const int b    = d_sched[blockIdx.x];

    int len = lengths[b];
    if (len > LL) len = LL;
    if (len < 1)  len = 1;

    // ---- transposed trans load + min/max fold (thread tid owns target column tid) ----
    {
        float mx = -3.4e38f, mn = 3.4e38f;
        #pragma unroll 4
        for (int i = 0; i < TT; ++i) {
            float v = trans[i * TT + tid];              // coalesced
            s_transT[tid * TSTRIDE + i] = v;            // stride-129 -> conflict-free
            mx = fmaxf(mx, v);
            mn = fminf(mn, v);
        }
        s_red[tid]       = mx;
        s_red[128 + tid] = mn;
    }
    if (tid < 2) s_cnt[tid] = 0;
    __syncthreads();

    // every thread folds the 256 staged values identically -> identical D everywhere
    float D;
    {
        float gmx = -3.4e38f, gmn = 3.4e38f;
        const float4* r4 = (const float4*)s_red;        // 16B-aligned broadcast reads
        #pragma unroll 8
        for (int k = 0; k < 32; ++k) {
            float4 a = r4[k];
            gmx = fmaxf(gmx, fmaxf(fmaxf(a.x, a.y), fmaxf(a.z, a.w)));
            float4 c = r4[32 + k];
            gmn = fminf(gmn, fminf(fminf(c.x, c.y), fminf(c.z, c.w)));
        }
        D = (gmx - gmn) * 1.001f + 0.01f;               // exact-pruning width + fp margin
        if (!(D >= 0.01f && D <= 1000.0f)) D = 3.0e38f; // dense fallback if anomalous
    }

    const float* xb = x + (size_t)b * (LL * TT);
    float sj = xb[tid];                                 // state_0[j]

    // depth-3 x prefetch (all guarded)
    float xA = (len > 1) ? xb[(size_t)1 * TT + tid] : 0.0f;
    float xB = (len > 2) ? xb[(size_t)2 * TT + tid] : 0.0f;
    float xC = (len > 3) ? xb[(size_t)3 * TT + tid] : 0.0f;

    // stage warp maxima of initial state for step 1
    {
        unsigned wm = __reduce_max_sync(FULL, fmap(sj));
        if (lane == 0) s_wmax[w] = wm;
    }
    const float* rowT = s_transT + tid * TSTRIDE;
    __syncthreads();                                    // entry barrier (BAR1 of t=1)

    for (int t = 1; t < len; ++t) {
        const int p = t & 1;

        // ---- phase B: threshold + survivor publish ----
        unsigned u0 = s_wmax[0], u1 = s_wmax[1], u2 = s_wmax[2], u3 = s_wmax[3];
        float thr = funmap(max(max(u0, u1), max(u2, u3))) - D;
        if (tid == 0) s_cnt[p ^ 1] = 0;                 // reset other buffer (safe post-BAR)
        if (sj >= thr) {
            int pos = atomicAdd(&s_cnt[p], 1);          // REDUX-aggregated; K ~ 2-4
            s_surv[(p << 7) + pos] = make_int2(__float_as_int(sj), tid);
        }
        __syncthreads();                                // BAR2

        // ---- phase A: survivor scan + state update ----
        const int K = s_cnt[p];                         // uniform -> converged loop
        float xcur = xA; xA = xB; xB = xC;
        xC = (t + 3 < len) ? xb[(size_t)(t + 3) * TT + tid] : 0.0f;

        float best = -3.4e38f;
        int   bi   = 0;
        for (int k = 0; k < K; ++k) {
            int2 pr = s_surv[(p << 7) + k];             // broadcast LDS.64 (8B-aligned)
            float v = __int_as_float(pr.x) + rowT[pr.y];
            upd(best, bi, v, pr.y);
        }

        s_bp[(t << 7) + tid] = (uint8_t)bi;
        sj = best + xcur;                               // reference op order

        unsigned wm = __reduce_max_sync(FULL, fmap(sj));
        if (lane == 0) s_wmax[w] = wm;
        __syncthreads();                                // BAR1 of next step (drains STS)
    }

    // ---- final argmax (first-max) + backward walk ----
    s_red[tid] = sj;
    __syncthreads();
    if (tid == 0) {
        float bestf = s_red[0];
        int cand = 0;
        for (int i = 1; i < TT; ++i) {
            float v = s_red[i];
            if (v > bestf) { bestf = v; cand = i; }
        }
        int carry = cand;
        for (int t = len - 1; t >= 1; --t) {
            s_tags[t] = carry;
            carry = (int)s_bp[(t << 7) + carry];
        }
        s_tags[0] = carry;
    }
    __syncthreads();

    // ---- output: float32 tags for t < len, zeros beyond ----
    float* orow = out + b * LL;
    #pragma unroll 2
    for (int k = tid; k < LL / 4; k += THREADS) {
        int base = k << 2;
        float4 v;
        v.x = (base + 0 < len) ? (float)s_tags[base + 0] : 0.0f;
        v.y = (base + 1 < len) ? (float)s_tags[base + 1] : 0.0f;
        v.z = (base + 2 < len) ? (float)s_tags[base + 2] : 0.0f;
        v.w = (base + 3 < len) ? (float)s_tags[base + 3] : 0.0f;
        ((float4*)orow)[k] = v;
    }
}

extern "C" void kernel_launch(void* const* d_in, const int* in_sizes, int n_in,
                              void* d_out, int out_size)
{
    const float* x       = nullptr;
    const int*   lengths = nullptr;
    const float* trans   = nullptr;
    for (int i = 0; i < n_in; ++i) {
        long s = in_sizes[i];
        if      (s == 33554432L || s == 134217728L) x       = (const float*)d_in[i];
        else if (s == 256L      || s == 1024L)      lengths = (const int*)d_in[i];
        else if (s == 16384L    || s == 65536L)     trans   = (const float*)d_in[i];
    }
    if (!x       && n_in > 0) x       = (const float*)d_in[0];
    if (!lengths && n_in > 1) lengths = (const int*)d_in[1];
    if (!trans   && n_in > 3) trans   = (const float*)d_in[3];

    sched_kernel<<<1, NB>>>(lengths);

    cudaFuncSetAttribute(crf_decode_kernel,
                         cudaFuncAttributeMaxDynamicSharedMemorySize, SMEM_BYTES);
    crf_decode_kernel<<<NB, THREADS, SMEM_BYTES>>>(x, lengths, trans, (float*)d_out);
}